// round 1
// baseline (speedup 1.0000x reference)
#include <cuda_runtime.h>
#include <cstdint>

#define N_NODES_MAX 100000
#define N_EDGES_MAX 1600000

// ---------------- scratch (static device globals; no allocations allowed) ---
__device__ float4  g_h[N_NODES_MAX * 16];     // [N,64] projected features
__device__ float4  g_el[N_NODES_MAX];         // [N,4] left attention halves
__device__ float4  g_er[N_NODES_MAX];         // [N,4] right attention halves
__device__ uint4   g_emax[N_NODES_MAX];       // [N,4] encoded segment max
__device__ float4  g_denom[N_NODES_MAX];      // [N,4] softmax denominators
__device__ float4  g_ex[N_EDGES_MAX];         // [E,4] exp(e - emax[dst])

// ---------------- helpers ---------------------------------------------------
__device__ __forceinline__ unsigned enc_f(float f) {
    unsigned u = __float_as_uint(f);
    return (u & 0x80000000u) ? ~u : (u | 0x80000000u);
}
__device__ __forceinline__ float dec_f(unsigned u) {
    return (u & 0x80000000u) ? __uint_as_float(u ^ 0x80000000u)
                             : __uint_as_float(~u);
}
__device__ __forceinline__ float leaky(float x) {
    return x > 0.f ? x : 0.2f * x;
}
__device__ __forceinline__ void red_add_f4(float4* p, float4 v) {
    asm volatile("red.global.add.v4.f32 [%0], {%1,%2,%3,%4};"
                 :: "l"(p), "f"(v.x), "f"(v.y), "f"(v.z), "f"(v.w)
                 : "memory");
}

// ---------------- kernel 0: init out=bias, emax=0(enc -inf floor), denom=0 --
__global__ void init_kernel(const float* __restrict__ bias,
                            float* __restrict__ out, int n_nodes) {
    int i = blockIdx.x * blockDim.x + threadIdx.x;
    if (i < n_nodes * 64) out[i] = bias[i & 63];
    if (i < n_nodes * 4) {
        ((unsigned*)g_emax)[i] = 0u;
        ((float*)g_denom)[i]   = 0.f;
    }
}

// ---------------- kernel 1: h = feat @ W, el/er = <h, attn_{l,r}> -----------
// block = 128 threads, one node per thread. Dynamic smem:
//   Wsh   [128*64]   (32KB)
//   alS   [64], arS [64]
//   featS [128*129]  (padded, 64.5KB) -- reused as h-transpose buffer (pad 65)
#define GEMM_SMEM_FLOATS (128 * 64 + 64 + 64 + 128 * 129)

__global__ __launch_bounds__(128)
void gemm_kernel(const float* __restrict__ feat, const float* __restrict__ W,
                 const float* __restrict__ attn_l, const float* __restrict__ attn_r,
                 int n_nodes) {
    extern __shared__ float smem[];
    float* Wsh   = smem;                   // 8192 floats
    float* alS   = smem + 8192;            // 64
    float* arS   = smem + 8256;            // 64
    float* featS = smem + 8320;            // 128*129

    const int tid  = threadIdx.x;
    const int base = blockIdx.x * 128;

    for (int i = tid; i < 128 * 64; i += 128) Wsh[i] = W[i];
    if (tid < 64) { alS[tid] = attn_l[tid]; arS[tid] = attn_r[tid]; }
    for (int i = tid; i < 128 * 128; i += 128) {
        int row = i >> 7, col = i & 127;
        int node = base + row;
        featS[row * 129 + col] = (node < n_nodes) ? feat[node * 128 + col] : 0.f;
    }
    __syncthreads();

    float acc[64];
#pragma unroll
    for (int c = 0; c < 64; c++) acc[c] = 0.f;

    const float4* Wsh4 = (const float4*)Wsh;
    for (int k = 0; k < 128; k++) {
        float f = featS[tid * 129 + k];
#pragma unroll
        for (int c4 = 0; c4 < 16; c4++) {
            float4 w = Wsh4[k * 16 + c4];
            acc[c4 * 4 + 0] += f * w.x;
            acc[c4 * 4 + 1] += f * w.y;
            acc[c4 * 4 + 2] += f * w.z;
            acc[c4 * 4 + 3] += f * w.w;
        }
    }

    // attention halves
    float el_[4], er_[4];
#pragma unroll
    for (int hd = 0; hd < 4; hd++) {
        float sl = 0.f, sr = 0.f;
#pragma unroll
        for (int d = 0; d < 16; d++) {
            sl += acc[hd * 16 + d] * alS[hd * 16 + d];
            sr += acc[hd * 16 + d] * arS[hd * 16 + d];
        }
        el_[hd] = sl; er_[hd] = sr;
    }

    const int node = base + tid;
    if (node < n_nodes) {
        g_el[node] = make_float4(el_[0], el_[1], el_[2], el_[3]);
        g_er[node] = make_float4(er_[0], er_[1], er_[2], er_[3]);
    }

    // transpose h through smem (reuse featS, pad 65) for coalesced stores
    __syncthreads();
#pragma unroll
    for (int c = 0; c < 64; c++) featS[tid * 65 + c] = acc[c];
    __syncthreads();
    float* g_h_f = (float*)g_h;
    for (int i = tid; i < 128 * 64; i += 128) {
        int row = i >> 6, col = i & 63;
        int nd = base + row;
        if (nd < n_nodes) g_h_f[nd * 64 + col] = featS[row * 65 + col];
    }
}

// ---------------- kernel 2: per-edge logits -> segment max ------------------
__global__ void edge_max_kernel(const int* __restrict__ src,
                                const int* __restrict__ dst, int n_edges) {
    int e = blockIdx.x * blockDim.x + threadIdx.x;
    if (e >= n_edges) return;
    int s = src[e], d = dst[e];
    float4 a = g_el[s];
    float4 b = g_er[d];
    unsigned* em = (unsigned*)&g_emax[d];
    atomicMax(em + 0, enc_f(leaky(a.x + b.x)));
    atomicMax(em + 1, enc_f(leaky(a.y + b.y)));
    atomicMax(em + 2, enc_f(leaky(a.z + b.z)));
    atomicMax(em + 3, enc_f(leaky(a.w + b.w)));
}

// ---------------- kernel 3: ex = exp(e - emax[dst]); denom += ex ------------
__global__ void edge_exp_kernel(const int* __restrict__ src,
                                const int* __restrict__ dst, int n_edges) {
    int e = blockIdx.x * blockDim.x + threadIdx.x;
    if (e >= n_edges) return;
    int s = src[e], d = dst[e];
    float4 a = g_el[s];
    float4 b = g_er[d];
    uint4  m = g_emax[d];
    float4 ex;
    ex.x = __expf(leaky(a.x + b.x) - dec_f(m.x));
    ex.y = __expf(leaky(a.y + b.y) - dec_f(m.y));
    ex.z = __expf(leaky(a.z + b.z) - dec_f(m.z));
    ex.w = __expf(leaky(a.w + b.w) - dec_f(m.w));
    g_ex[e] = ex;
    red_add_f4(&g_denom[d], ex);
}

// ---------------- kernel 4: out[dst] += alpha * h[src] ----------------------
// one thread per (edge, head): loads 64B of h[src], scatters 64B via red.v4
__global__ void edge_agg_kernel(const int* __restrict__ src,
                                const int* __restrict__ dst,
                                float* __restrict__ out, int n_edges) {
    int idx = blockIdx.x * blockDim.x + threadIdx.x;
    if (idx >= n_edges * 4) return;
    int e = idx >> 2, h = idx & 3;
    int s = src[e], d = dst[e];
    float alpha = ((const float*)&g_ex[e])[h] / ((const float*)&g_denom[d])[h];
    const float4* hp = g_h + (s * 16 + h * 4);
    float4*       op = (float4*)out + (d * 16 + h * 4);
#pragma unroll
    for (int j = 0; j < 4; j++) {
        float4 v = hp[j];
        v.x *= alpha; v.y *= alpha; v.z *= alpha; v.w *= alpha;
        red_add_f4(op + j, v);
    }
}

// ---------------- launcher --------------------------------------------------
extern "C" void kernel_launch(void* const* d_in, const int* in_sizes, int n_in,
                              void* d_out, int out_size) {
    const float* feat   = (const float*)d_in[0];
    const float* W      = (const float*)d_in[1];
    const float* attn_l = (const float*)d_in[2];
    const float* attn_r = (const float*)d_in[3];
    const float* bias   = (const float*)d_in[4];
    const int*   src    = (const int*)d_in[5];
    const int*   dst    = (const int*)d_in[6];
    float*       out    = (float*)d_out;

    const int n_nodes = in_sizes[0] / 128;
    const int n_edges = in_sizes[5];

    cudaFuncSetAttribute(gemm_kernel, cudaFuncAttributeMaxDynamicSharedMemorySize,
                         GEMM_SMEM_FLOATS * (int)sizeof(float));

    init_kernel<<<(n_nodes * 64 + 255) / 256, 256>>>(bias, out, n_nodes);
    gemm_kernel<<<(n_nodes + 127) / 128, 128,
                  GEMM_SMEM_FLOATS * (int)sizeof(float)>>>(feat, W, attn_l,
                                                           attn_r, n_nodes);
    edge_max_kernel<<<(n_edges + 255) / 256, 256>>>(src, dst, n_edges);
    edge_exp_kernel<<<(n_edges + 255) / 256, 256>>>(src, dst, n_edges);
    edge_agg_kernel<<<(n_edges * 4 + 255) / 256, 256>>>(src, dst, out, n_edges);
}

// round 2
// speedup vs baseline: 1.4118x; 1.4118x over previous
#include <cuda_runtime.h>
#include <cstdint>
#include <cfloat>

#define N_NODES_MAX 100000
#define N_EDGES_MAX 1600000
#define FULL 0xFFFFFFFFu

// ---------------- scratch (static device globals) ---------------------------
__device__ float4  g_h[N_NODES_MAX * 16];     // [N,64] projected features
__device__ float4  g_el[N_NODES_MAX];         // [N,4]
__device__ float4  g_er[N_NODES_MAX];         // [N,4]
__device__ float4  g_ex[N_EDGES_MAX];         // [E,4] logits -> exp (CSR order)
__device__ int     g_cnt[N_NODES_MAX];        // in-degree
__device__ int     g_fill[N_NODES_MAX];       // scatter cursors
__device__ int     g_rowptr[N_NODES_MAX];     // exclusive prefix of cnt
__device__ int     g_blksum[128];
__device__ int     g_esrc[N_EDGES_MAX];       // CSR: src node per slot

__device__ __forceinline__ float leaky(float x) { return x > 0.f ? x : 0.2f * x; }

// ---------------- kernel: zero counters -------------------------------------
__global__ void zero_kernel(int n_nodes) {
    int i = blockIdx.x * blockDim.x + threadIdx.x;
    if (i < n_nodes) { g_cnt[i] = 0; g_fill[i] = 0; }
}

// ---------------- kernel: in-degree histogram -------------------------------
__global__ void hist_kernel(const int* __restrict__ dst, int n_edges) {
    int e = blockIdx.x * blockDim.x + threadIdx.x;
    if (e < n_edges) atomicAdd(&g_cnt[dst[e]], 1);
}

// ---------------- scan (3 kernels): rowptr = exclusive_scan(cnt) ------------
__global__ __launch_bounds__(1024) void scan1_kernel(int n) {
    __shared__ int sh[1024];
    int i = blockIdx.x * 1024 + threadIdx.x;
    int v = (i < n) ? g_cnt[i] : 0;
    sh[threadIdx.x] = v;
    __syncthreads();
    for (int off = 1; off < 1024; off <<= 1) {
        int t = (threadIdx.x >= off) ? sh[threadIdx.x - off] : 0;
        __syncthreads();
        sh[threadIdx.x] += t;
        __syncthreads();
    }
    if (i < n) g_rowptr[i] = sh[threadIdx.x] - v;
    if (threadIdx.x == 1023) g_blksum[blockIdx.x] = sh[1023];
}
__global__ void scan2_kernel(int nb) {
    __shared__ int sh[128];
    int t = threadIdx.x;
    int v = (t < nb) ? g_blksum[t] : 0;
    sh[t] = v;
    __syncthreads();
    for (int off = 1; off < 128; off <<= 1) {
        int u = (t >= off) ? sh[t - off] : 0;
        __syncthreads();
        sh[t] += u;
        __syncthreads();
    }
    if (t < nb) g_blksum[t] = sh[t] - v;   // exclusive
}
__global__ __launch_bounds__(1024) void scan3_kernel(int n) {
    int i = blockIdx.x * 1024 + threadIdx.x;
    if (i < n) g_rowptr[i] += g_blksum[blockIdx.x];
}

// ---------------- kernel: CSR scatter ----------------------------------------
__global__ void scatter_kernel(const int* __restrict__ src,
                               const int* __restrict__ dst, int n_edges) {
    int e = blockIdx.x * blockDim.x + threadIdx.x;
    if (e >= n_edges) return;
    int d = dst[e];
    int r = atomicAdd(&g_fill[d], 1);
    g_esrc[g_rowptr[d] + r] = src[e];
}

// ---------------- kernel: h = feat @ W, el/er --------------------------------
#define GEMM_SMEM_FLOATS (128 * 64 + 64 + 64 + 128 * 129)
__global__ __launch_bounds__(128)
void gemm_kernel(const float* __restrict__ feat, const float* __restrict__ W,
                 const float* __restrict__ attn_l, const float* __restrict__ attn_r,
                 int n_nodes) {
    extern __shared__ float smem[];
    float* Wsh   = smem;
    float* alS   = smem + 8192;
    float* arS   = smem + 8256;
    float* featS = smem + 8320;

    const int tid  = threadIdx.x;
    const int base = blockIdx.x * 128;

    for (int i = tid; i < 128 * 64; i += 128) Wsh[i] = W[i];
    if (tid < 64) { alS[tid] = attn_l[tid]; arS[tid] = attn_r[tid]; }
    for (int i = tid; i < 128 * 128; i += 128) {
        int row = i >> 7, col = i & 127;
        int node = base + row;
        featS[row * 129 + col] = (node < n_nodes) ? feat[node * 128 + col] : 0.f;
    }
    __syncthreads();

    float acc[64];
#pragma unroll
    for (int c = 0; c < 64; c++) acc[c] = 0.f;

    const float4* Wsh4 = (const float4*)Wsh;
    for (int k = 0; k < 128; k++) {
        float f = featS[tid * 129 + k];
#pragma unroll
        for (int c4 = 0; c4 < 16; c4++) {
            float4 w = Wsh4[k * 16 + c4];
            acc[c4 * 4 + 0] += f * w.x;
            acc[c4 * 4 + 1] += f * w.y;
            acc[c4 * 4 + 2] += f * w.z;
            acc[c4 * 4 + 3] += f * w.w;
        }
    }

    float el_[4], er_[4];
#pragma unroll
    for (int hd = 0; hd < 4; hd++) {
        float sl = 0.f, sr = 0.f;
#pragma unroll
        for (int d = 0; d < 16; d++) {
            sl += acc[hd * 16 + d] * alS[hd * 16 + d];
            sr += acc[hd * 16 + d] * arS[hd * 16 + d];
        }
        el_[hd] = sl; er_[hd] = sr;
    }

    const int node = base + tid;
    if (node < n_nodes) {
        g_el[node] = make_float4(el_[0], el_[1], el_[2], el_[3]);
        g_er[node] = make_float4(er_[0], er_[1], er_[2], er_[3]);
    }

    __syncthreads();
#pragma unroll
    for (int c = 0; c < 64; c++) featS[tid * 65 + c] = acc[c];
    __syncthreads();
    float* g_h_f = (float*)g_h;
    for (int i = tid; i < 128 * 64; i += 128) {
        int row = i >> 6, col = i & 63;
        int nd = base + row;
        if (nd < n_nodes) g_h_f[nd * 64 + col] = featS[row * 65 + col];
    }
}

// ---------------- kernel: per-node softmax + aggregation (one warp/node) ----
__global__ __launch_bounds__(256)
void node_kernel(const float* __restrict__ bias, float* __restrict__ out,
                 int n_nodes) {
    const int gwarp = (blockIdx.x * blockDim.x + threadIdx.x) >> 5;
    const int lane  = threadIdx.x & 31;
    if (gwarp >= n_nodes) return;

    const int base = g_rowptr[gwarp];
    const int deg  = g_cnt[gwarp];
    const float4 er4 = g_er[gwarp];

    // pass 1: logits -> g_ex, running max
    float4 mx = make_float4(-FLT_MAX, -FLT_MAX, -FLT_MAX, -FLT_MAX);
    for (int i = lane; i < deg; i += 32) {
        int s = g_esrc[base + i];
        float4 a = g_el[s];
        float4 lg;
        lg.x = leaky(a.x + er4.x); lg.y = leaky(a.y + er4.y);
        lg.z = leaky(a.z + er4.z); lg.w = leaky(a.w + er4.w);
        g_ex[base + i] = lg;
        mx.x = fmaxf(mx.x, lg.x); mx.y = fmaxf(mx.y, lg.y);
        mx.z = fmaxf(mx.z, lg.z); mx.w = fmaxf(mx.w, lg.w);
    }
#pragma unroll
    for (int o = 16; o; o >>= 1) {
        mx.x = fmaxf(mx.x, __shfl_xor_sync(FULL, mx.x, o));
        mx.y = fmaxf(mx.y, __shfl_xor_sync(FULL, mx.y, o));
        mx.z = fmaxf(mx.z, __shfl_xor_sync(FULL, mx.z, o));
        mx.w = fmaxf(mx.w, __shfl_xor_sync(FULL, mx.w, o));
    }

    // pass 2: exp + denom (each lane rereads only its own slots)
    float4 sm = make_float4(0.f, 0.f, 0.f, 0.f);
    for (int i = lane; i < deg; i += 32) {
        float4 lg = g_ex[base + i];
        float4 ex;
        ex.x = __expf(lg.x - mx.x); ex.y = __expf(lg.y - mx.y);
        ex.z = __expf(lg.z - mx.z); ex.w = __expf(lg.w - mx.w);
        g_ex[base + i] = ex;
        sm.x += ex.x; sm.y += ex.y; sm.z += ex.z; sm.w += ex.w;
    }
#pragma unroll
    for (int o = 16; o; o >>= 1) {
        sm.x += __shfl_xor_sync(FULL, sm.x, o);
        sm.y += __shfl_xor_sync(FULL, sm.y, o);
        sm.z += __shfl_xor_sync(FULL, sm.z, o);
        sm.w += __shfl_xor_sync(FULL, sm.w, o);
    }
    __syncwarp();   // fence: cross-lane reads of g_ex in pass 3

    // pass 3: aggregation. lane owns cols 2*lane, 2*lane+1; head = lane>>3.
    const int hd = lane >> 3;
    const float rd = 1.f / (hd == 0 ? sm.x : hd == 1 ? sm.y : hd == 2 ? sm.z : sm.w);
    const float*  exf = (const float*)g_ex;
    const float2* h2  = (const float2*)g_h;
    float2 acc = make_float2(0.f, 0.f);
    int i = 0;
    for (; i + 1 < deg; i += 2) {
        int s0 = g_esrc[base + i];
        int s1 = g_esrc[base + i + 1];
        float a0 = exf[(base + i) * 4 + hd] * rd;
        float a1 = exf[(base + i + 1) * 4 + hd] * rd;
        float2 v0 = h2[s0 * 32 + lane];
        float2 v1 = h2[s1 * 32 + lane];
        acc.x += a0 * v0.x + a1 * v1.x;
        acc.y += a0 * v0.y + a1 * v1.y;
    }
    if (i < deg) {
        int s0 = g_esrc[base + i];
        float a0 = exf[(base + i) * 4 + hd] * rd;
        float2 v0 = h2[s0 * 32 + lane];
        acc.x += a0 * v0.x;
        acc.y += a0 * v0.y;
    }

    float2 b2 = ((const float2*)bias)[lane];
    ((float2*)out)[gwarp * 32 + lane] = make_float2(acc.x + b2.x, acc.y + b2.y);
}

// ---------------- launcher --------------------------------------------------
extern "C" void kernel_launch(void* const* d_in, const int* in_sizes, int n_in,
                              void* d_out, int out_size) {
    const float* feat   = (const float*)d_in[0];
    const float* W      = (const float*)d_in[1];
    const float* attn_l = (const float*)d_in[2];
    const float* attn_r = (const float*)d_in[3];
    const float* bias   = (const float*)d_in[4];
    const int*   src    = (const int*)d_in[5];
    const int*   dst    = (const int*)d_in[6];
    float*       out    = (float*)d_out;

    const int n_nodes = in_sizes[0] / 128;
    const int n_edges = in_sizes[5];
    const int nb      = (n_nodes + 1023) / 1024;

    cudaFuncSetAttribute(gemm_kernel, cudaFuncAttributeMaxDynamicSharedMemorySize,
                         GEMM_SMEM_FLOATS * (int)sizeof(float));

    zero_kernel<<<(n_nodes + 255) / 256, 256>>>(n_nodes);
    hist_kernel<<<(n_edges + 255) / 256, 256>>>(dst, n_edges);
    scan1_kernel<<<nb, 1024>>>(n_nodes);
    scan2_kernel<<<1, 128>>>(nb);
    scan3_kernel<<<nb, 1024>>>(n_nodes);
    scatter_kernel<<<(n_edges + 255) / 256, 256>>>(src, dst, n_edges);
    gemm_kernel<<<(n_nodes + 127) / 128, 128,
                  GEMM_SMEM_FLOATS * (int)sizeof(float)>>>(feat, W, attn_l,
                                                           attn_r, n_nodes);
    node_kernel<<<(n_nodes * 32 + 255) / 256, 256>>>(bias, out, n_nodes);
}